// round 13
// baseline (speedup 1.0000x reference)
#include <cuda_runtime.h>
#include <math.h>

// Problem constants (fixed by the dataset)
#define BB 2
#define HH 16
#define NN 8192
#define HD 128
#define NOFF 20

#define FULLMASK 0xffffffffu

// 8-lane groups; one query per group; 4 queries per warp
#define QW 4
#define NWARP 8
#define QB (QW * NWARP)   // 32 queries per block

// delta -> offset index
__device__ __host__ __forceinline__ constexpr int j_of(int d) {
    switch (d) {
        case 1: return 0;  case 2: return 1;  case 3: return 2;  case 4: return 3;
        case 5: return 4;  case 6: return 5;  case 7: return 6;  case 8: return 7;
        case 9: return 8;  case 11: return 9; case 13: return 10; case 15: return 11;
        case 16: return 12; case 23: return 13; case 32: return 14; case 64: return 15;
        case 128: return 16; case 256: return 17; case 512: return 18; case 1024: return 19;
        default: return -1;
    }
}

__device__ __forceinline__ float dot4_acc(float acc, float4 a, float4 b) {
    acc = fmaf(a.x, b.x, acc);
    acc = fmaf(a.y, b.y, acc);
    acc = fmaf(a.z, b.z, acc);
    acc = fmaf(a.w, b.w, acc);
    return acc;
}

// 3-stage butterfly within the 8-lane group; result replicated in all 8 lanes
__device__ __forceinline__ float group_sum(float p) {
    p += __shfl_xor_sync(FULLMASK, p, 1);
    p += __shfl_xor_sync(FULLMASK, p, 2);
    p += __shfl_xor_sync(FULLMASK, p, 4);
    return p;
}

__global__ void __launch_bounds__(256)
dsqg_kernel(const float* __restrict__ q,
            const float* __restrict__ k,
            const float* __restrict__ v,
            const float* __restrict__ pb,   // [J, H]
            const float* __restrict__ se,   // [J, HD]
            float* __restrict__ out)
{
    // near band (dense reuse across the 4 consecutive queries of a warp)
    const int NEAR_D[13] = {1,2,3,4,5,6,7,8,9,11,13,15,16};
    const int FAR_D[7]   = {23,32,64,128,256,512,1024};

    const int lane = threadIdx.x & 31;
    const int s    = lane & 7;        // position within 8-lane group
    const int g    = lane >> 3;       // query within warp
    const int warp = threadIdx.x >> 5;

    // bh fastest in blockIdx -> concurrent wave covers a narrow n-window over all
    // (b,h): keeps the delta<=1024 reuse window resident in L2.
    const int bh   = blockIdx.x & (BB * HH - 1);
    const int tile = blockIdx.x >> 5;
    const int h    = bh & (HH - 1);
    const int nq0  = tile * QB + warp * QW;   // first query of this warp
    const int nq   = nq0 + g;                 // this group's query

    const size_t base = (size_t)bh * ((size_t)NN * HD);
    const float* qr    = q + base + (size_t)nq * HD;
    const float* kbase = k + base;
    const float* vbase = v + base;
    float*       orow  = out + base + (size_t)nq * HD;

    const float sc = 0.08838834764831845f;  // 1/sqrt(128)
    const float NEG_INF = __int_as_float(0xff800000);

    // dense group access: load i covers float4-chunk i*8+s (one 128B line / 8 lanes)
#define CHUNK(i) (((i) * 8 + s) * 4)

    float4 qa[4];
#pragma unroll
    for (int i = 0; i < 4; ++i)
        qa[i] = *(const float4*)(qr + CHUNK(i));

    float S[NOFF];
#pragma unroll
    for (int j = 0; j < NOFF; ++j) S[j] = NEG_INF;

    // ---- Phase 1: near-band bias. S[j] = sc*(q.se_j) + pb[j,h] (valid pairs only).
    // se row is identical across groups -> broadcast loads (1 line per chunk).
#pragma unroll
    for (int jj = 0; jj < 13; ++jj) {
        const int dlt = NEAR_D[jj];
        const int j   = j_of(dlt);
        const float* srow = se + j * HD;
        float p = 0.f;
#pragma unroll
        for (int i = 0; i < 4; ++i) p = dot4_acc(p, qa[i], *(const float4*)(srow + CHUNK(i)));
        p = group_sum(p);
        if (nq >= dlt) S[j] = fmaf(sc, p, pb[j * HH + h]);  // group-uniform predicate
    }

    // ---- Phase 2: near-band k via diagonals. Row nq0-c is loaded ONCE per warp
    // (broadcast across groups) and serves every pair (g, delta=c+g) on the diagonal.
#pragma unroll
    for (int c = -2; c <= 16; ++c) {
        if (nq0 >= c) {                       // warp-uniform: all pairs on diagonal valid
            const float* krow = kbase + (size_t)(nq0 - c) * HD;
            float p = 0.f;
#pragma unroll
            for (int i = 0; i < 4; ++i) p = dot4_acc(p, qa[i], *(const float4*)(krow + CHUNK(i)));
            p = group_sum(p);
            // commit: group gp targets j = j_of(c+gp) when c+gp is a near delta
#pragma unroll
            for (int gp = 0; gp < 4; ++gp) {
                const int d = c + gp;
                if (d >= 1 && d <= 16) {
                    const int j = j_of(d);
                    if (j >= 0 && j < 13) {
                        if (g == gp) S[j] = fmaf(sc, p, S[j]);
                    }
                }
            }
        }
    }

    // ---- Phase 3: far offsets, per-group rows (no reuse available); se folded in.
#pragma unroll
    for (int jj = 0; jj < 7; ++jj) {
        const int dlt = FAR_D[jj];
        const int j   = j_of(dlt);
        const int row  = nq - dlt;
        const int rowc = row < 0 ? 0 : row;
        const float* krow = kbase + (size_t)rowc * HD;
        const float* srow = se + j * HD;
        float p = 0.f;
#pragma unroll
        for (int i = 0; i < 4; ++i) p = dot4_acc(p, qa[i], *(const float4*)(krow + CHUNK(i)));
#pragma unroll
        for (int i = 0; i < 4; ++i) p = dot4_acc(p, qa[i], *(const float4*)(srow + CHUNK(i)));
        p = group_sum(p);
        if (row >= 0) S[j] = fmaf(sc, p, pb[j * HH + h]);   // group-uniform
    }

    // ---- softmax over the 20 offsets: pure register math (S group-replicated) ----
    float mx = S[0];
#pragma unroll
    for (int j = 1; j < NOFF; ++j) mx = fmaxf(mx, S[j]);
    const float ms = (mx == NEG_INF) ? 0.f : mx;
    float P[NOFF];
    float sum = 0.f;
#pragma unroll
    for (int j = 0; j < NOFF; ++j) {
        const float e = __expf(S[j] - ms);   // exp(-inf) -> 0 for invalid offsets
        P[j] = e;
        sum += e;
    }
    const float inv = (sum > 0.f) ? (1.0f / sum) : 0.f;
#pragma unroll
    for (int j = 0; j < NOFF; ++j) P[j] *= inv;

    float4 o[4];
#pragma unroll
    for (int i = 0; i < 4; ++i) { o[i].x = 0.f; o[i].y = 0.f; o[i].z = 0.f; o[i].w = 0.f; }

    // ---- Phase 5: near-band v via the same diagonals (row broadcast across groups) ----
#pragma unroll
    for (int c = -2; c <= 16; ++c) {
        if (nq0 >= c) {
            const float* vrow = vbase + (size_t)(nq0 - c) * HD;
            float w = 0.f;
#pragma unroll
            for (int gp = 0; gp < 4; ++gp) {
                const int d = c + gp;
                if (d >= 1 && d <= 16) {
                    const int j = j_of(d);
                    if (j >= 0 && j < 13) w = (g == gp) ? P[j] : w;
                }
            }
#pragma unroll
            for (int i = 0; i < 4; ++i) {
                const float4 v4 = *(const float4*)(vrow + CHUNK(i));
                o[i].x = fmaf(w, v4.x, o[i].x);
                o[i].y = fmaf(w, v4.y, o[i].y);
                o[i].z = fmaf(w, v4.z, o[i].z);
                o[i].w = fmaf(w, v4.w, o[i].w);
            }
        }
    }

    // ---- Phase 6: far v, per-group rows (invalid j has P[j] == 0) ----
#pragma unroll
    for (int jj = 0; jj < 7; ++jj) {
        const int dlt = FAR_D[jj];
        const int j   = j_of(dlt);
        const int row  = nq - dlt;
        const int rowc = row < 0 ? 0 : row;
        const float pj = P[j];
        const float* vrow = vbase + (size_t)rowc * HD;
#pragma unroll
        for (int i = 0; i < 4; ++i) {
            const float4 v4 = *(const float4*)(vrow + CHUNK(i));
            o[i].x = fmaf(pj, v4.x, o[i].x);
            o[i].y = fmaf(pj, v4.y, o[i].y);
            o[i].z = fmaf(pj, v4.z, o[i].z);
            o[i].w = fmaf(pj, v4.w, o[i].w);
        }
    }

#pragma unroll
    for (int i = 0; i < 4; ++i)
        *(float4*)(orow + CHUNK(i)) = o[i];

#undef CHUNK
}

extern "C" void kernel_launch(void* const* d_in, const int* in_sizes, int n_in,
                              void* d_out, int out_size) {
    const float* q  = (const float*)d_in[0];
    const float* k  = (const float*)d_in[1];
    const float* v  = (const float*)d_in[2];
    const float* pb = (const float*)d_in[3];
    const float* se = (const float*)d_in[4];
    float* out = (float*)d_out;

    // 32 queries per block; bh fastest in blockIdx for L2 window locality
    const int nblocks = (BB * HH) * (NN / QB);   // 32 * 256 = 8192
    dsqg_kernel<<<nblocks, 256>>>(q, k, v, pb, se, out);
}